// round 9
// baseline (speedup 1.0000x reference)
#include <cuda_runtime.h>
#include <cuda.h>
#include <cuda_bf16.h>
#include <cuda_fp8.h>
#include <stdint.h>

#define M_DIM 8192
#define K_DIM 4096
#define N_DIM 4096
#define GPR (K_DIM / 16)   // 256 groups/row
#define GWR (K_DIM / 64)   // 64 SF words/row

#if defined(__CUDA_ARCH__) && (__CUDA_ARCH__ >= 1000) && \
    (defined(__CUDA_ARCH_FEAT_SM103_ALL) || defined(__CUDA_ARCH_FEAT_SM100_ALL) || \
     defined(__CUDA_ARCH_SPECIFIC__) || defined(__CUDA_ARCH_FAMILY_SPECIFIC__))
#define USE_TCGEN05 1
#else
#define USE_TCGEN05 0
#endif

// ---------------- scratch ----------------
__device__ uint64_t g_xq4[(size_t)M_DIM * GPR];   // packed e2m1 x, 16 MB
__device__ uint64_t g_wq4[(size_t)N_DIM * GPR];   // packed e2m1 w,  8 MB
__device__ uint32_t g_sfa[(size_t)GWR * M_DIM];   // SF words [gw][m]
__device__ uint32_t g_sfb[(size_t)GWR * N_DIM];   // SF words [gw][n]
__device__ unsigned int g_tile_ctr;
__constant__ float c_lut[8] = {0.f, 0.5f, 1.f, 1.5f, 2.f, 3.f, 4.f, 6.f};

__global__ void reset_ctr_kernel() { g_tile_ctr = 0u; }

__device__ __forceinline__ uint32_t smem_u32(const void* p) {
    uint32_t a;
    asm("{ .reg .u64 t; cvta.to.shared.u64 t, %1; cvt.u32.u64 %0, t; }" : "=r"(a) : "l"(p));
    return a;
}

#if USE_TCGEN05
__device__ __forceinline__ uint32_t elect_one_pred() {
    uint32_t pred;
    asm volatile("{\n\t.reg .pred p;\n\telect.sync _|p, 0xFFFFFFFF;\n\t"
                 "selp.b32 %0, 1, 0, p;\n\t}" : "=r"(pred));
    return pred;
}

__device__ __forceinline__ uint32_t cluster_ctarank() {
    uint32_t r;
    asm("mov.u32 %0, %%cluster_ctarank;" : "=r"(r));
    return r;
}

#define CLUSTER_SYNC() do { \
    asm volatile("barrier.cluster.arrive.aligned;" ::: "memory"); \
    asm volatile("barrier.cluster.wait.aligned;" ::: "memory"); \
} while (0)

#define ST_SLOT_REMOTE(addr, val) \
    asm volatile("{\n\t.reg .b32 ra;\n\tmapa.shared::cluster.u32 ra, %0, 1;\n\t" \
        "st.shared::cluster.u32 [ra], %1;\n\t}" \
        :: "r"((uint32_t)(addr)), "r"((uint32_t)(val)) : "memory")

#define MBARRIER_INIT(addr, cnt) \
    asm volatile("mbarrier.init.shared.b64 [%0], %1;" :: "r"((uint32_t)(addr)), "r"((uint32_t)(cnt)) : "memory")
#define MBARRIER_ARRIVE(addr) \
    asm volatile("mbarrier.arrive.shared.b64 _, [%0];" :: "r"((uint32_t)(addr)) : "memory")
#define MBARRIER_EXPECT_TX(addr, bytes) \
    asm volatile("mbarrier.arrive.expect_tx.shared.b64 _, [%0], %1;" \
        :: "r"((uint32_t)(addr)), "r"((uint32_t)(bytes)) : "memory")
#define MBARRIER_WAIT_PARITY(mbar_smem_addr, phase_parity) do { \
    uint32_t _mbar = (uint32_t)(mbar_smem_addr); \
    uint32_t _parity = (uint32_t)(phase_parity); \
    uint32_t _done; \
    asm volatile("{\n\t.reg .pred p;\n\t" \
        "mbarrier.try_wait.parity.acquire.cta.shared::cta.b64 p, [%1], %2;\n\t" \
        "selp.b32 %0, 1, 0, p;\n\t}" : "=r"(_done) : "r"(_mbar), "r"(_parity) : "memory"); \
    if (!_done) { \
        asm volatile("{\n\t.reg .pred P1;\n\t" \
            "WAIT_LOOP_%=:\n\t" \
            "mbarrier.try_wait.parity.acquire.cta.shared::cta.b64 P1, [%0], %1, 0x989680;\n\t" \
            "@P1 bra.uni WAIT_DONE_%=;\n\t" \
            "bra.uni WAIT_LOOP_%=;\n\t" \
            "WAIT_DONE_%=:\n\t}" :: "r"(_mbar), "r"(_parity) : "memory"); \
    } \
} while (0)

#define TMA_LOAD_2D(smem_addr, map_ptr, cx, cy, mbar) \
    asm volatile("cp.async.bulk.tensor.2d.shared::cta.global.tile.mbarrier::complete_tx::bytes " \
        "[%0], [%1, {%2, %3}], [%4];" \
        :: "r"((uint32_t)(smem_addr)), "l"(map_ptr), "r"((int)(cx)), "r"((int)(cy)), \
           "r"((uint32_t)(mbar)) : "memory")

#define TMA_LOAD_2D_MC(smem_addr, map_ptr, cx, cy, mbar, mask) \
    asm volatile("cp.async.bulk.tensor.2d.shared::cluster.global.tile.mbarrier::complete_tx::bytes.multicast::cluster " \
        "[%0], [%1, {%2, %3}], [%4], %5;" \
        :: "r"((uint32_t)(smem_addr)), "l"(map_ptr), "r"((int)(cx)), "r"((int)(cy)), \
           "r"((uint32_t)(mbar)), "h"((uint16_t)(mask)) : "memory")

#define TCGEN05_ALLOC(a, n) \
    asm volatile("tcgen05.alloc.cta_group::1.sync.aligned.shared::cta.b32 [%0], %1;" \
        :: "r"((uint32_t)(a)), "r"((uint32_t)(n)) : "memory")
#define TCGEN05_DEALLOC(t, n) \
    asm volatile("tcgen05.dealloc.cta_group::1.sync.aligned.b32 %0, %1;" :: "r"(t), "r"((uint32_t)(n)))
#define TCGEN05_RELINQUISH() \
    asm volatile("tcgen05.relinquish_alloc_permit.cta_group::1.sync.aligned;")
#define TCGEN05_COMMIT(m) \
    asm volatile("tcgen05.commit.cta_group::1.mbarrier::arrive::one.shared::cluster.b64 [%0];" \
        :: "r"((uint32_t)(m)) : "memory")
#define TCGEN05_COMMIT_MC(m, mask) \
    asm volatile("tcgen05.commit.cta_group::1.mbarrier::arrive::one.shared::cluster.multicast::cluster.b64 [%0], %1;" \
        :: "r"((uint32_t)(m)), "h"((uint16_t)(mask)) : "memory")
#define TCGEN05_WAIT_LD() asm volatile("tcgen05.wait::ld.sync.aligned;" ::: "memory")
#define TCGEN05_WAIT_ST() asm volatile("tcgen05.wait::st.sync.aligned;" ::: "memory")
#define TCGEN05_FENCE_AFTER()  asm volatile("tcgen05.fence::after_thread_sync;" ::: "memory")
#define TCGEN05_FENCE_BEFORE() asm volatile("tcgen05.fence::before_thread_sync;" ::: "memory")

#define LDS32(r, addr) \
    asm volatile("ld.shared.b32 %0, [%1];" : "=r"(r) : "r"((uint32_t)(addr)))

#define TCGEN05_LD_32X32B_X32(r, tmem_addr) \
    asm volatile("tcgen05.ld.sync.aligned.32x32b.x32.b32 " \
        "{%0, %1, %2, %3, %4, %5, %6, %7, " \
        " %8, %9, %10, %11, %12, %13, %14, %15, " \
        " %16, %17, %18, %19, %20, %21, %22, %23, " \
        " %24, %25, %26, %27, %28, %29, %30, %31}, [%32];" \
        : "=r"((r)[0]),  "=r"((r)[1]),  "=r"((r)[2]),  "=r"((r)[3]), \
          "=r"((r)[4]),  "=r"((r)[5]),  "=r"((r)[6]),  "=r"((r)[7]), \
          "=r"((r)[8]),  "=r"((r)[9]),  "=r"((r)[10]), "=r"((r)[11]), \
          "=r"((r)[12]), "=r"((r)[13]), "=r"((r)[14]), "=r"((r)[15]), \
          "=r"((r)[16]), "=r"((r)[17]), "=r"((r)[18]), "=r"((r)[19]), \
          "=r"((r)[20]), "=r"((r)[21]), "=r"((r)[22]), "=r"((r)[23]), \
          "=r"((r)[24]), "=r"((r)[25]), "=r"((r)[26]), "=r"((r)[27]), \
          "=r"((r)[28]), "=r"((r)[29]), "=r"((r)[30]), "=r"((r)[31]) \
        : "r"(tmem_addr))

__device__ __forceinline__ void ttst4(uint32_t addr, uint32_t r0, uint32_t r1,
                                      uint32_t r2, uint32_t r3) {
    asm volatile("tcgen05.st.sync.aligned.32x32b.x4.b32 [%0], {%1, %2, %3, %4};"
        :: "r"(addr), "r"(r0), "r"(r1), "r"(r2), "r"(r3) : "memory");
}

__device__ __forceinline__ uint64_t make_desc(uint32_t addr) {
    const uint64_t base = (2ull << 61) | (1ull << 46) | (64ull << 32) | (1ull << 16);
    return base | ((uint64_t)(addr >> 4) & 0x3FFFull);
}

__device__ __forceinline__ void mma_nvf4_ss(uint32_t d, uint64_t a_desc, uint64_t b_desc,
                                            uint32_t idesc, uint32_t sfa, uint32_t sfb,
                                            uint32_t acc) {
    asm volatile("{\n\t.reg .pred p;\n\tsetp.ne.u32 p, %6, 0;\n\t"
        "tcgen05.mma.cta_group::1.kind::mxf4nvf4.block_scale.scale_vec::4X "
        "[%0], %1, %2, %3, [%4], [%5], p;\n\t}"
        :: "r"(d), "l"(a_desc), "l"(b_desc), "r"(idesc), "r"(sfa), "r"(sfb), "r"(acc)
        : "memory");
}
#endif  // USE_TCGEN05

// ---------------- quant: fp32 -> packed e2m1 + e4m3 SF (bit-exact, proven) ----
__global__ void __launch_bounds__(256) quant_fp4_kernel(const float* __restrict__ in,
                                                        uint64_t* __restrict__ outq,
                                                        uint8_t* __restrict__ sfp,
                                                        int nrows, int ngroups) {
    int g = blockIdx.x * blockDim.x + threadIdx.x;
    if (g >= ngroups) return;

    const float4* p = reinterpret_cast<const float4*>(in) + (size_t)g * 4;
    float v[16];
    {
        float4 t0 = p[0], t1 = p[1], t2 = p[2], t3 = p[3];
        v[0]=t0.x; v[1]=t0.y; v[2]=t0.z;  v[3]=t0.w;
        v[4]=t1.x; v[5]=t1.y; v[6]=t1.z;  v[7]=t1.w;
        v[8]=t2.x; v[9]=t2.y; v[10]=t2.z; v[11]=t2.w;
        v[12]=t3.x; v[13]=t3.y; v[14]=t3.z; v[15]=t3.w;
    }
    float amax = 0.0f;
    #pragma unroll
    for (int i = 0; i < 16; i++) amax = fmaxf(amax, fabsf(v[i]));

    float sraw = __fdiv_rn(amax, 6.0f);
    __nv_fp8_e4m3 s8(sraw);
    float scale = float(s8);

    uint64_t pack = 0;
    if (scale > 0.0f) {
        const float t0 = 0.25f * scale, t1 = 0.75f * scale, t2 = 1.25f * scale,
                    t3 = 1.75f * scale, t4 = 2.5f * scale,  t5 = 3.5f * scale,
                    t6 = 5.0f * scale;
        #pragma unroll
        for (int i = 0; i < 16; i++) {
            float a = fabsf(v[i]);
            uint32_t code;
            if      (a < t0) code = 0u;
            else if (a < t1) code = 1u;
            else if (a < t2) code = 2u;
            else if (a < t3) code = 3u;
            else if (a < t4) code = 4u;
            else if (a < t5) code = 5u;
            else if (a < t6) code = 6u;
            else             code = 7u;
            if (v[i] < 0.0f) code |= 8u;
            pack |= (uint64_t)code << (4 * i);
        }
    }
    outq[g] = pack;

    int m = g / GPR;
    int G = g % GPR;
    sfp[(((size_t)(G >> 2)) * (size_t)nrows + (size_t)m) * 4 + (size_t)(G & 3)] = s8.__x;
}

// ---------------- GEMM ----------------
#define BM 128
#define BN 256
#define GEMM_THREADS 256
#define NCHUNK 16
#define NT_X (N_DIM / BN)               // 16
#define NTILES ((M_DIM / BM) * NT_X)    // 1024
#define NPAIRS (NTILES / 2)             // 512 (two M-tiles sharing an N-panel)
#define NSTAGE 4
#define A_BYTES 16384
#define B_BYTES 32768
#define SFA_OFF (A_BYTES + B_BYTES)     // 49152
#define SFB_OFF (SFA_OFF + 2048)        // 51200
#define STAGE_BYTES 55296
#define STAGE_TX 55296
#define TMEM_SF 256
#define SF_COLS 48
#define GEMM_IDESC ((1u << 7) | (1u << 10) | (16u << 17) | (1u << 27))
#define HDR_OFF (NSTAGE * STAGE_BYTES)  // 221184
#define GEMM_SMEM_BYTES (HDR_OFF + 128 + 1024)

#if USE_TCGEN05
// SF warps: SMEM slab -> TMEM. B slab is now two 2KB slices (cols 0-127 / 128-255),
// each 4 rows x 128 u32 contiguous. Logical TMEM layout unchanged from R8.
__device__ __forceinline__ void sf_fill_smem(uint32_t tmem, int s, uint32_t sa,
                                             int lid, uint32_t warp_off) {
    const uint32_t sfbase = tmem + TMEM_SF + (uint32_t)s * SF_COLS;
    const uint32_t pA = sa + SFA_OFF;
    const uint32_t pB = sa + SFB_OFF;
    #pragma unroll
    for (int ks = 0; ks < 4; ks++) {
        uint32_t a0, a1, a2, a3;
        LDS32(a0, pA + (uint32_t)(ks * 128 +   0 + lid) * 4u);
        LDS32(a1, pA + (uint32_t)(ks * 128 +  32 + lid) * 4u);
        LDS32(a2, pA + (uint32_t)(ks * 128 +  64 + lid) * 4u);
        LDS32(a3, pA + (uint32_t)(ks * 128 +  96 + lid) * 4u);
        ttst4(sfbase + (uint32_t)(ks * 4) + warp_off, a0, a1, a2, a3);
        uint32_t b[8];
        #pragma unroll
        for (int j = 0; j < 8; j++) {
            const uint32_t region = (uint32_t)(j >> 2) * 2048u;
            const uint32_t local  = (uint32_t)((j & 3) * 32 + lid);
            LDS32(b[j], pB + region + (uint32_t)(ks * 512) + local * 4u);
        }
        ttst4(sfbase + 16u + (uint32_t)(ks * 8) + warp_off,      b[0], b[1], b[2], b[3]);
        ttst4(sfbase + 16u + (uint32_t)(ks * 8) + 4u + warp_off, b[4], b[5], b[6], b[7]);
    }
    TCGEN05_WAIT_ST();
}
#endif

__global__ void __launch_bounds__(GEMM_THREADS, 1) __cluster_dims__(2, 1, 1)
gemm_fp4(const __grid_constant__ CUtensorMap mapA,
         const __grid_constant__ CUtensorMap mapB,
         const __grid_constant__ CUtensorMap mapSA,
         const __grid_constant__ CUtensorMap mapSB,
         const float* __restrict__ bias,
         float* __restrict__ out)
{
    extern __shared__ char smem_raw[];
    const int tid = threadIdx.x;
    const int wid = tid >> 5;
    const int lid = tid & 31;

#if USE_TCGEN05
    const uint32_t rank = cluster_ctarank();
    const uint32_t base = (smem_u32(smem_raw) + 1023u) & ~1023u;
    const uint32_t hdr = base + HDR_OFF;
    const uint32_t tmem_ptr_addr = hdr;
    const uint32_t full0    = hdr + 16u;
    const uint32_t empty0   = hdr + 48u;
    const uint32_t sf_full0 = hdr + 80u;
    const uint32_t doneb    = hdr + 112u;
    const uint32_t slot     = hdr + 120u;

    if (wid == 0) TCGEN05_ALLOC(tmem_ptr_addr, 512);
    if (tid == 0) {
        #pragma unroll
        for (int s = 0; s < NSTAGE; s++) {
            MBARRIER_INIT(full0    + (uint32_t)s * 8u, 1);
            MBARRIER_INIT(empty0   + (uint32_t)s * 8u, 2);   // both consumers (multicast commit)
            MBARRIER_INIT(sf_full0 + (uint32_t)s * 8u, 4);
        }
        MBARRIER_INIT(doneb, 1);
    }
    __syncthreads();
    if (rank == 0 && tid == 0) {
        unsigned int t0 = atomicAdd(&g_tile_ctr, 1u);
        asm volatile("st.shared.u32 [%0], %1;" :: "r"(slot), "r"(t0) : "memory");
        ST_SLOT_REMOTE(slot, t0);
    }
    CLUSTER_SYNC();   // barriers valid cluster-wide + initial claim published

    uint32_t tmem;
    asm volatile("ld.shared.b32 %0, [%1];" : "=r"(tmem) : "r"(tmem_ptr_addr));
    uint32_t t;
    asm volatile("ld.shared.u32 %0, [%1];" : "=r"(t) : "r"(slot));

    const uint32_t warp_off = (uint32_t)(wid & 3) << 21;
    uint32_t gc = 0;          // s = gc&3, parity = (gc>>2)&1
    uint32_t tile_cnt = 0;
    bool first = true;

    while (t < NPAIRS) {
        if (rank == 0 && tid == 0) {
            unsigned int tn_ = atomicAdd(&g_tile_ctr, 1u);
            asm volatile("st.shared.u32 [%0], %1;" :: "r"(slot), "r"(tn_) : "memory");
            ST_SLOT_REMOTE(slot, tn_);
        }
        CLUSTER_SYNC();   // publishes tn; also orders prev epilogue before next MMAs
        uint32_t tn;
        asm volatile("ld.shared.u32 %0, [%1];" : "=r"(tn) : "r"(slot));

        const int m0  = ((int)(t / NT_X) * 2 + (int)rank) * BM;
        const int n0  = (int)(t % NT_X) * BN;
        const int m0n = ((int)(tn / NT_X) * 2 + (int)rank) * BM;   // valid iff tn < NPAIRS
        const int n0n = (int)(tn % NT_X) * BN;
        const uint32_t bslice  = A_BYTES + rank * 16384u;
        const uint32_t sbslice = SFB_OFF + rank * 2048u;
        const int bofs = (int)rank * 128;

        if (first) {
            if (wid == 1 && elect_one_pred()) {
                #pragma unroll
                for (int p = 0; p < NSTAGE; p++) {
                    const uint32_t fb = full0 + (uint32_t)p * 8u;
                    const uint32_t sa = base + (uint32_t)p * STAGE_BYTES;
                    MBARRIER_EXPECT_TX(fb, STAGE_TX);
                    TMA_LOAD_2D(sa,           &mapA,  p * 128,    m0,    fb);
                    TMA_LOAD_2D(sa + SFA_OFF, &mapSA, m0,         p * 4, fb);
                    TMA_LOAD_2D_MC(sa + bslice,  &mapB,  p * 128,    n0 + bofs, fb, 3);
                    TMA_LOAD_2D_MC(sa + sbslice, &mapSB, n0 + bofs,  p * 4,     fb, 3);
                }
            } else if (wid >= 4) {
                #pragma unroll
                for (int p = 0; p < NSTAGE; p++) {
                    const uint32_t sa = base + (uint32_t)p * STAGE_BYTES;
                    MBARRIER_WAIT_PARITY(full0 + (uint32_t)p * 8u, 0u);
                    sf_fill_smem(tmem, p, sa, lid, warp_off);
                    TCGEN05_FENCE_BEFORE();
                    if (lid == 0) MBARRIER_ARRIVE(sf_full0 + (uint32_t)p * 8u);
                }
            }
            first = false;
        }

        for (int c = 0; c < NCHUNK; c++, gc++) {
            const int s = (int)(gc & 3u);
            const uint32_t par = (gc >> 2) & 1u;
            const uint32_t sa = base + (uint32_t)s * STAGE_BYTES;

            if (wid == 0) {
                if (elect_one_pred()) {
                    MBARRIER_WAIT_PARITY(sf_full0 + (uint32_t)s * 8u, par);
                    TCGEN05_FENCE_AFTER();
                    const uint64_t ad  = make_desc(sa);
                    const uint64_t bd0 = make_desc(sa + 16384u);
                    const uint64_t bd1 = make_desc(sa + 32768u);
                    const uint32_t sfbase = tmem + TMEM_SF + (uint32_t)s * SF_COLS;
                    #pragma unroll
                    for (int ks = 0; ks < 4; ks++) {
                        const uint32_t acc = (c > 0 || ks > 0) ? 1u : 0u;
                        const uint64_t ka = (uint64_t)(ks * 2);
                        const uint32_t sfa  = sfbase + (uint32_t)(ks * 4);
                        const uint32_t sfb0 = sfbase + 16u + (uint32_t)(ks * 8);
                        mma_nvf4_ss(tmem + 0u,   ad + ka, bd0 + ka, GEMM_IDESC, sfa, sfb0,      acc);
                        mma_nvf4_ss(tmem + 128u, ad + ka, bd1 + ka, GEMM_IDESC, sfa, sfb0 + 4u, acc);
                    }
                    TCGEN05_COMMIT_MC(empty0 + (uint32_t)s * 8u, 3);   // both CTAs' empty(s)
                }
            } else if (wid == 1) {
                if (elect_one_pred()) {
                    int cc = c + NSTAGE, kx, ya, yb;
                    bool valid;
                    if (cc < NCHUNK)      { valid = true;  kx = cc;          ya = m0;  yb = n0;  }
                    else if (tn < NPAIRS) { valid = true;  kx = cc - NCHUNK; ya = m0n; yb = n0n; }
                    else                  { valid = false; kx = 0; ya = 0; yb = 0; }
                    if (valid) {
                        MBARRIER_WAIT_PARITY(empty0 + (uint32_t)s * 8u, par);  // both consumers done
                        MBARRIER_EXPECT_TX(full0 + (uint32_t)s * 8u, STAGE_TX);
                        TMA_LOAD_2D(sa,           &mapA,  kx * 128,  ya,     full0 + (uint32_t)s * 8u);
                        TMA_LOAD_2D(sa + SFA_OFF, &mapSA, ya,        kx * 4, full0 + (uint32_t)s * 8u);
                        TMA_LOAD_2D_MC(sa + bslice,  &mapB,  kx * 128,  yb + bofs, full0 + (uint32_t)s * 8u, 3);
                        TMA_LOAD_2D_MC(sa + sbslice, &mapSB, yb + bofs, kx * 4,    full0 + (uint32_t)s * 8u, 3);
                    }
                }
            } else if (wid >= 4) {
                int cc = c + NSTAGE;
                bool valid = (cc < NCHUNK) || (tn < NPAIRS);
                if (valid) {
                    MBARRIER_WAIT_PARITY(empty0 + (uint32_t)s * 8u, par);        // TMEM free
                    MBARRIER_WAIT_PARITY(full0  + (uint32_t)s * 8u, par ^ 1u);   // slab arrived
                    sf_fill_smem(tmem, s, sa, lid, warp_off);
                    TCGEN05_FENCE_BEFORE();
                    if (lid == 0) MBARRIER_ARRIVE(sf_full0 + (uint32_t)s * 8u);
                }
            }
        }

        // Tile-done (per-CTA): one regular commit after all chunks; alias-safe per R5.
        if (wid == 0 && elect_one_pred()) TCGEN05_COMMIT(doneb);
        MBARRIER_WAIT_PARITY(doneb, tile_cnt & 1u);
        tile_cnt++;
        TCGEN05_FENCE_AFTER();

        // Epilogue (per-CTA): warp w -> rows m0+(w&3)*32+lid, cols (w>>2)*128..+127.
        {
            const int m = m0 + (wid & 3) * 32 + lid;
            const int nb = n0 + (wid >> 2) * 128;
            const uint32_t dbase = tmem + (uint32_t)((wid >> 2) * 128);
            float* orow = out + (size_t)m * N_DIM + nb;
            for (int cc2 = 0; cc2 < 128; cc2 += 32) {
                uint32_t d[32];
                TCGEN05_LD_32X32B_X32(d, dbase + (uint32_t)cc2);
                TCGEN05_WAIT_LD();
                const float4* b4 = reinterpret_cast<const float4*>(bias + nb + cc2);
                float4* o4 = reinterpret_cast<float4*>(orow + cc2);
                #pragma unroll
                for (int q = 0; q < 8; q++) {
                    float4 bv = __ldg(b4 + q);
                    float4 ov;
                    ov.x = __uint_as_float(d[q * 4 + 0]) + bv.x;
                    ov.y = __uint_as_float(d[q * 4 + 1]) + bv.y;
                    ov.z = __uint_as_float(d[q * 4 + 2]) + bv.z;
                    ov.w = __uint_as_float(d[q * 4 + 3]) + bv.w;
                    o4[q] = ov;
                }
            }
            TCGEN05_FENCE_BEFORE();
        }

        t = tn;
    }

    CLUSTER_SYNC();   // no CTA exits while peer multicast could still target its SMEM
    if (wid == 0) {
        TCGEN05_RELINQUISH();
        TCGEN05_DEALLOC(tmem, 512);
    }

#else
    // ------- baseline-pass fallback: correct SIMT decode GEMM (never selected) -------
    const int tt = blockIdx.x;
    const int m0 = (tt / NT_X) * BM;
    const int n0 = (tt % NT_X) * BN;
    for (int idx = tid; idx < BM * BN; idx += GEMM_THREADS) {
        const int m = m0 + idx / BN;
        const int n = n0 + idx % BN;
        float acc = 0.0f;
        for (int G = 0; G < GPR; G++) {
            uint64_t av = g_xq4[(size_t)m * GPR + G];
            uint64_t bv = g_wq4[(size_t)n * GPR + G];
            __nv_fp8_e4m3 sa8, sb8;
            sa8.__x = (uint8_t)(g_sfa[(size_t)(G >> 2) * M_DIM + m] >> ((G & 3) * 8));
            sb8.__x = (uint8_t)(g_sfb[(size_t)(G >> 2) * N_DIM + n] >> ((G & 3) * 8));
            float fs = float(sa8) * float(sb8);
            float sum = 0.0f;
            #pragma unroll
            for (int i = 0; i < 16; i++) {
                uint32_t ca = (uint32_t)(av >> (4 * i)) & 15u;
                uint32_t cb = (uint32_t)(bv >> (4 * i)) & 15u;
                float va = c_lut[ca & 7u]; if (ca & 8u) va = -va;
                float vb = c_lut[cb & 7u]; if (cb & 8u) vb = -vb;
                sum += va * vb;
            }
            acc += sum * fs;
        }
        out[(size_t)m * N_DIM + n] = acc + __ldg(bias + n);
    }
#endif
}

// ---------------- host: tensormap encode ----------------
typedef CUresult (*PFN_encodeTiled)(
    CUtensorMap*, CUtensorMapDataType, cuuint32_t, void*,
    const cuuint64_t*, const cuuint64_t*, const cuuint32_t*, const cuuint32_t*,
    CUtensorMapInterleave, CUtensorMapSwizzle, CUtensorMapL2promotion,
    CUtensorMapFloatOOBfill);

static PFN_encodeTiled get_encoder() {
    void* p = nullptr;
    cudaDriverEntryPointQueryResult st;
    cudaGetDriverEntryPointByVersion("cuTensorMapEncodeTiled", &p, 12000,
                                     cudaEnableDefault, &st);
    return (PFN_encodeTiled)p;
}

static void encode_map_u8(CUtensorMap* map, void* ptr, uint64_t rows,
                          uint64_t row_bytes, uint32_t box_rows) {
    cuuint64_t dims[2]    = {row_bytes, rows};
    cuuint64_t strides[1] = {row_bytes};
    cuuint32_t box[2]     = {128, box_rows};
    cuuint32_t estr[2]    = {1, 1};
    get_encoder()(map, CU_TENSOR_MAP_DATA_TYPE_UINT8, 2, ptr,
       dims, strides, box, estr,
       CU_TENSOR_MAP_INTERLEAVE_NONE, CU_TENSOR_MAP_SWIZZLE_128B,
       CU_TENSOR_MAP_L2_PROMOTION_L2_128B,
       CU_TENSOR_MAP_FLOAT_OOB_FILL_NONE);
}

static void encode_map_sf(CUtensorMap* map, void* ptr, uint64_t cols, uint32_t box_cols) {
    cuuint64_t dims[2]    = {cols, GWR};
    cuuint64_t strides[1] = {cols * 4};
    cuuint32_t box[2]     = {box_cols, 4};
    cuuint32_t estr[2]    = {1, 1};
    get_encoder()(map, CU_TENSOR_MAP_DATA_TYPE_UINT32, 2, ptr,
       dims, strides, box, estr,
       CU_TENSOR_MAP_INTERLEAVE_NONE, CU_TENSOR_MAP_SWIZZLE_NONE,
       CU_TENSOR_MAP_L2_PROMOTION_L2_128B,
       CU_TENSOR_MAP_FLOAT_OOB_FILL_NONE);
}

// ---------------- launcher ----------------
extern "C" void kernel_launch(void* const* d_in, const int* in_sizes, int n_in,
                              void* d_out, int out_size) {
    (void)in_sizes; (void)n_in; (void)out_size;
    const float* x    = (const float*)d_in[0];
    const float* w    = (const float*)d_in[1];
    const float* bias = (const float*)d_in[2];
    float* out = (float*)d_out;

    uint64_t *xq4 = nullptr, *wq4 = nullptr;
    uint32_t *sfa = nullptr, *sfb = nullptr;
    cudaGetSymbolAddress((void**)&xq4, g_xq4);
    cudaGetSymbolAddress((void**)&wq4, g_wq4);
    cudaGetSymbolAddress((void**)&sfa, g_sfa);
    cudaGetSymbolAddress((void**)&sfb, g_sfb);

    CUtensorMap mapA, mapB, mapSA, mapSB;
    encode_map_u8(&mapA, xq4, M_DIM, K_DIM / 2, 128);
    encode_map_u8(&mapB, wq4, N_DIM, K_DIM / 2, 128);   // 128-row slice (multicast)
    encode_map_sf(&mapSA, sfa, M_DIM, 128);
    encode_map_sf(&mapSB, sfb, N_DIM, 128);             // 128-col slice (multicast)

    const int xg = M_DIM * GPR;
    const int wg = N_DIM * GPR;
    quant_fp4_kernel<<<xg / 256, 256>>>(x, xq4, (uint8_t*)sfa, M_DIM, xg);
    quant_fp4_kernel<<<wg / 256, 256>>>(w, wq4, (uint8_t*)sfb, N_DIM, wg);

    reset_ctr_kernel<<<1, 1>>>();

    cudaFuncSetAttribute(gemm_fp4, cudaFuncAttributeMaxDynamicSharedMemorySize, GEMM_SMEM_BYTES);
    gemm_fp4<<<NTILES, GEMM_THREADS, GEMM_SMEM_BYTES>>>(mapA, mapB, mapSA, mapSB, bias, out);
}

// round 10
// speedup vs baseline: 1.0202x; 1.0202x over previous
#include <cuda_runtime.h>
#include <cuda.h>
#include <cuda_bf16.h>
#include <cuda_fp8.h>
#include <stdint.h>

#define M_DIM 8192
#define K_DIM 4096
#define N_DIM 4096
#define GPR (K_DIM / 16)   // 256 groups/row
#define GWR (K_DIM / 64)   // 64 SF words/row

#if defined(__CUDA_ARCH__) && (__CUDA_ARCH__ >= 1000) && \
    (defined(__CUDA_ARCH_FEAT_SM103_ALL) || defined(__CUDA_ARCH_FEAT_SM100_ALL) || \
     defined(__CUDA_ARCH_SPECIFIC__) || defined(__CUDA_ARCH_FAMILY_SPECIFIC__))
#define USE_TCGEN05 1
#else
#define USE_TCGEN05 0
#endif

// ---------------- scratch ----------------
__device__ uint64_t g_xq4[(size_t)M_DIM * GPR];   // packed e2m1 x, 16 MB
__device__ uint64_t g_wq4[(size_t)N_DIM * GPR];   // packed e2m1 w,  8 MB
__device__ uint32_t g_sfa[(size_t)GWR * M_DIM];   // SF words [gw][m]
__device__ uint32_t g_sfb[(size_t)GWR * N_DIM];   // SF words [gw][n]
__device__ unsigned int g_tile_ctr;
__constant__ float c_lut[8] = {0.f, 0.5f, 1.f, 1.5f, 2.f, 3.f, 4.f, 6.f};

__global__ void reset_ctr_kernel() { g_tile_ctr = 0u; }

__device__ __forceinline__ uint32_t smem_u32(const void* p) {
    uint32_t a;
    asm("{ .reg .u64 t; cvta.to.shared.u64 t, %1; cvt.u32.u64 %0, t; }" : "=r"(a) : "l"(p));
    return a;
}

#if USE_TCGEN05
__device__ __forceinline__ uint32_t elect_one_pred() {
    uint32_t pred;
    asm volatile("{\n\t.reg .pred p;\n\telect.sync _|p, 0xFFFFFFFF;\n\t"
                 "selp.b32 %0, 1, 0, p;\n\t}" : "=r"(pred));
    return pred;
}

__device__ __forceinline__ uint32_t cluster_ctarank() {
    uint32_t r;
    asm("mov.u32 %0, %%cluster_ctarank;" : "=r"(r));
    return r;
}

#define CLUSTER_SYNC() do { \
    asm volatile("barrier.cluster.arrive.aligned;" ::: "memory"); \
    asm volatile("barrier.cluster.wait.aligned;" ::: "memory"); \
} while (0)

#define ST_SLOT_REMOTE(addr, val) \
    asm volatile("{\n\t.reg .b32 ra;\n\tmapa.shared::cluster.u32 ra, %0, 1;\n\t" \
        "st.shared::cluster.u32 [ra], %1;\n\t}" \
        :: "r"((uint32_t)(addr)), "r"((uint32_t)(val)) : "memory")

// Arrive on the mbarrier at the same SMEM offset in cluster CTA 0.
#define MBARRIER_ARRIVE_RANK0(local_mbar_addr) \
    asm volatile("{\n\t.reg .b32 ra;\n\tmapa.shared::cluster.u32 ra, %0, 0;\n\t" \
        "mbarrier.arrive.shared::cluster.b64 _, [ra];\n\t}" \
        :: "r"((uint32_t)(local_mbar_addr)) : "memory")

#define MBARRIER_INIT(addr, cnt) \
    asm volatile("mbarrier.init.shared.b64 [%0], %1;" :: "r"((uint32_t)(addr)), "r"((uint32_t)(cnt)) : "memory")
#define MBARRIER_ARRIVE(addr) \
    asm volatile("mbarrier.arrive.shared.b64 _, [%0];" :: "r"((uint32_t)(addr)) : "memory")
#define MBARRIER_EXPECT_TX(addr, bytes) \
    asm volatile("mbarrier.arrive.expect_tx.shared.b64 _, [%0], %1;" \
        :: "r"((uint32_t)(addr)), "r"((uint32_t)(bytes)) : "memory")
#define MBARRIER_WAIT_PARITY(mbar_smem_addr, phase_parity) do { \
    uint32_t _mbar = (uint32_t)(mbar_smem_addr); \
    uint32_t _parity = (uint32_t)(phase_parity); \
    uint32_t _done; \
    asm volatile("{\n\t.reg .pred p;\n\t" \
        "mbarrier.try_wait.parity.acquire.cta.shared::cta.b64 p, [%1], %2;\n\t" \
        "selp.b32 %0, 1, 0, p;\n\t}" : "=r"(_done) : "r"(_mbar), "r"(_parity) : "memory"); \
    if (!_done) { \
        asm volatile("{\n\t.reg .pred P1;\n\t" \
            "WAIT_LOOP_%=:\n\t" \
            "mbarrier.try_wait.parity.acquire.cta.shared::cta.b64 P1, [%0], %1, 0x989680;\n\t" \
            "@P1 bra.uni WAIT_DONE_%=;\n\t" \
            "bra.uni WAIT_LOOP_%=;\n\t" \
            "WAIT_DONE_%=:\n\t}" :: "r"(_mbar), "r"(_parity) : "memory"); \
    } \
} while (0)

#define TMA_LOAD_2D(smem_addr, map_ptr, cx, cy, mbar) \
    asm volatile("cp.async.bulk.tensor.2d.shared::cta.global.tile.mbarrier::complete_tx::bytes " \
        "[%0], [%1, {%2, %3}], [%4];" \
        :: "r"((uint32_t)(smem_addr)), "l"(map_ptr), "r"((int)(cx)), "r"((int)(cy)), \
           "r"((uint32_t)(mbar)) : "memory")

#define TCGEN05_ALLOC_CG2(a, n) \
    asm volatile("tcgen05.alloc.cta_group::2.sync.aligned.shared::cta.b32 [%0], %1;" \
        :: "r"((uint32_t)(a)), "r"((uint32_t)(n)) : "memory")
#define TCGEN05_DEALLOC_CG2(t, n) \
    asm volatile("tcgen05.dealloc.cta_group::2.sync.aligned.b32 %0, %1;" :: "r"(t), "r"((uint32_t)(n)))
#define TCGEN05_RELINQUISH_CG2() \
    asm volatile("tcgen05.relinquish_alloc_permit.cta_group::2.sync.aligned;")
#define TCGEN05_COMMIT_MC_CG2(m, mask) \
    asm volatile("tcgen05.commit.cta_group::2.mbarrier::arrive::one.shared::cluster.multicast::cluster.b64 [%0], %1;" \
        :: "r"((uint32_t)(m)), "h"((uint16_t)(mask)) : "memory")
#define TCGEN05_WAIT_LD() asm volatile("tcgen05.wait::ld.sync.aligned;" ::: "memory")
#define TCGEN05_WAIT_ST() asm volatile("tcgen05.wait::st.sync.aligned;" ::: "memory")
#define TCGEN05_FENCE_AFTER()  asm volatile("tcgen05.fence::after_thread_sync;" ::: "memory")
#define TCGEN05_FENCE_BEFORE() asm volatile("tcgen05.fence::before_thread_sync;" ::: "memory")

#define LDS32(r, addr) \
    asm volatile("ld.shared.b32 %0, [%1];" : "=r"(r) : "r"((uint32_t)(addr)))

#define TCGEN05_LD_32X32B_X32(r, tmem_addr) \
    asm volatile("tcgen05.ld.sync.aligned.32x32b.x32.b32 " \
        "{%0, %1, %2, %3, %4, %5, %6, %7, " \
        " %8, %9, %10, %11, %12, %13, %14, %15, " \
        " %16, %17, %18, %19, %20, %21, %22, %23, " \
        " %24, %25, %26, %27, %28, %29, %30, %31}, [%32];" \
        : "=r"((r)[0]),  "=r"((r)[1]),  "=r"((r)[2]),  "=r"((r)[3]), \
          "=r"((r)[4]),  "=r"((r)[5]),  "=r"((r)[6]),  "=r"((r)[7]), \
          "=r"((r)[8]),  "=r"((r)[9]),  "=r"((r)[10]), "=r"((r)[11]), \
          "=r"((r)[12]), "=r"((r)[13]), "=r"((r)[14]), "=r"((r)[15]), \
          "=r"((r)[16]), "=r"((r)[17]), "=r"((r)[18]), "=r"((r)[19]), \
          "=r"((r)[20]), "=r"((r)[21]), "=r"((r)[22]), "=r"((r)[23]), \
          "=r"((r)[24]), "=r"((r)[25]), "=r"((r)[26]), "=r"((r)[27]), \
          "=r"((r)[28]), "=r"((r)[29]), "=r"((r)[30]), "=r"((r)[31]) \
        : "r"(tmem_addr))

__device__ __forceinline__ void ttst4(uint32_t addr, uint32_t r0, uint32_t r1,
                                      uint32_t r2, uint32_t r3) {
    asm volatile("tcgen05.st.sync.aligned.32x32b.x4.b32 [%0], {%1, %2, %3, %4};"
        :: "r"(addr), "r"(r0), "r"(r1), "r"(r2), "r"(r3) : "memory");
}

__device__ __forceinline__ uint64_t make_desc(uint32_t addr) {
    const uint64_t base = (2ull << 61) | (1ull << 46) | (64ull << 32) | (1ull << 16);
    return base | ((uint64_t)(addr >> 4) & 0x3FFFull);
}

// cg2 nvf4 block-scaled MMA: M=256 across pair, B split N/2 per CTA.
__device__ __forceinline__ void mma_nvf4_ss_cg2(uint32_t d, uint64_t a_desc, uint64_t b_desc,
                                                uint32_t idesc, uint32_t sfa, uint32_t sfb,
                                                uint32_t acc) {
    asm volatile("{\n\t.reg .pred p;\n\tsetp.ne.u32 p, %6, 0;\n\t"
        "tcgen05.mma.cta_group::2.kind::mxf4nvf4.block_scale.scale_vec::4X "
        "[%0], %1, %2, %3, [%4], [%5], p;\n\t}"
        :: "r"(d), "l"(a_desc), "l"(b_desc), "r"(idesc), "r"(sfa), "r"(sfb), "r"(acc)
        : "memory");
}
#endif  // USE_TCGEN05

// ---------------- quant: fp32 -> packed e2m1 + e4m3 SF (bit-exact, proven) ----
__global__ void __launch_bounds__(256) quant_fp4_kernel(const float* __restrict__ in,
                                                        uint64_t* __restrict__ outq,
                                                        uint8_t* __restrict__ sfp,
                                                        int nrows, int ngroups) {
    int g = blockIdx.x * blockDim.x + threadIdx.x;
    if (g >= ngroups) return;

    const float4* p = reinterpret_cast<const float4*>(in) + (size_t)g * 4;
    float v[16];
    {
        float4 t0 = p[0], t1 = p[1], t2 = p[2], t3 = p[3];
        v[0]=t0.x; v[1]=t0.y; v[2]=t0.z;  v[3]=t0.w;
        v[4]=t1.x; v[5]=t1.y; v[6]=t1.z;  v[7]=t1.w;
        v[8]=t2.x; v[9]=t2.y; v[10]=t2.z; v[11]=t2.w;
        v[12]=t3.x; v[13]=t3.y; v[14]=t3.z; v[15]=t3.w;
    }
    float amax = 0.0f;
    #pragma unroll
    for (int i = 0; i < 16; i++) amax = fmaxf(amax, fabsf(v[i]));

    float sraw = __fdiv_rn(amax, 6.0f);
    __nv_fp8_e4m3 s8(sraw);
    float scale = float(s8);

    uint64_t pack = 0;
    if (scale > 0.0f) {
        const float t0 = 0.25f * scale, t1 = 0.75f * scale, t2 = 1.25f * scale,
                    t3 = 1.75f * scale, t4 = 2.5f * scale,  t5 = 3.5f * scale,
                    t6 = 5.0f * scale;
        #pragma unroll
        for (int i = 0; i < 16; i++) {
            float a = fabsf(v[i]);
            uint32_t code;
            if      (a < t0) code = 0u;
            else if (a < t1) code = 1u;
            else if (a < t2) code = 2u;
            else if (a < t3) code = 3u;
            else if (a < t4) code = 4u;
            else if (a < t5) code = 5u;
            else if (a < t6) code = 6u;
            else             code = 7u;
            if (v[i] < 0.0f) code |= 8u;
            pack |= (uint64_t)code << (4 * i);
        }
    }
    outq[g] = pack;

    int m = g / GPR;
    int G = g % GPR;
    sfp[(((size_t)(G >> 2)) * (size_t)nrows + (size_t)m) * 4 + (size_t)(G & 3)] = s8.__x;
}

// ---------------- GEMM (cg2: 256x256 tile per cluster pair) ----------------
#define GEMM_THREADS 256
#define NCHUNK 16
#define NT_X (N_DIM / 256)               // 16
#define NPAIRS ((M_DIM / 256) * NT_X)    // 512 pair-tiles
#define NSTAGE 5
#define A_BYTES 16384                    // 128 rows x 128B per CTA
#define B_BYTES 16384                    // 128 N-rows (own half) per CTA
#define SFA_OFF (A_BYTES + B_BYTES)      // 32768 (2K: own 128 rows)
#define SFB_OFF (SFA_OFF + 2048)         // 34816 (4K: full N=256)
#define STAGE_BYTES 38912
#define STAGE_TX 38912
#define TMEM_SF 256
#define SF_COLS 48
// idesc: atype=btype=E2M1(1), N=256 -> 32<<17, UE4M3 (bit23=0), M=256 -> 2<<27
#define GEMM_IDESC ((1u << 7) | (1u << 10) | (32u << 17) | (2u << 27))
#define HDR_OFF (NSTAGE * STAGE_BYTES)   // 194560
#define GEMM_SMEM_BYTES (HDR_OFF + 256 + 1024)

#if USE_TCGEN05
// SF warps: SMEM slab -> TMEM (per-CTA layout byte-identical to proven R8 scheme:
// SFA = own 128 rows, SFB = full N=256 replicated across subpartitions).
__device__ __forceinline__ void sf_fill_smem(uint32_t tmem, int s, uint32_t sa,
                                             int lid, uint32_t warp_off) {
    const uint32_t sfbase = tmem + TMEM_SF + (uint32_t)s * SF_COLS;
    const uint32_t pA = sa + SFA_OFF;
    const uint32_t pB = sa + SFB_OFF;
    #pragma unroll
    for (int ks = 0; ks < 4; ks++) {
        uint32_t a0, a1, a2, a3;
        LDS32(a0, pA + (uint32_t)(ks * 128 +   0 + lid) * 4u);
        LDS32(a1, pA + (uint32_t)(ks * 128 +  32 + lid) * 4u);
        LDS32(a2, pA + (uint32_t)(ks * 128 +  64 + lid) * 4u);
        LDS32(a3, pA + (uint32_t)(ks * 128 +  96 + lid) * 4u);
        ttst4(sfbase + (uint32_t)(ks * 4) + warp_off, a0, a1, a2, a3);
        uint32_t b[8];
        #pragma unroll
        for (int j = 0; j < 8; j++)
            LDS32(b[j], pB + (uint32_t)(ks * 256 + j * 32 + lid) * 4u);
        ttst4(sfbase + 16u + (uint32_t)(ks * 8) + warp_off,      b[0], b[1], b[2], b[3]);
        ttst4(sfbase + 16u + (uint32_t)(ks * 8) + 4u + warp_off, b[4], b[5], b[6], b[7]);
    }
    TCGEN05_WAIT_ST();
}
#endif

__global__ void __launch_bounds__(GEMM_THREADS, 1) __cluster_dims__(2, 1, 1)
gemm_fp4(const __grid_constant__ CUtensorMap mapA,
         const __grid_constant__ CUtensorMap mapB,
         const __grid_constant__ CUtensorMap mapSA,
         const __grid_constant__ CUtensorMap mapSB,
         const float* __restrict__ bias,
         float* __restrict__ out)
{
    extern __shared__ char smem_raw[];
    const int tid = threadIdx.x;
    const int wid = tid >> 5;
    const int lid = tid & 31;

#if USE_TCGEN05
    const uint32_t rank = cluster_ctarank();
    const uint32_t base = (smem_u32(smem_raw) + 1023u) & ~1023u;
    const uint32_t hdr = base + HDR_OFF;
    const uint32_t tmem_ptr_addr = hdr;
    const uint32_t full0    = hdr + 16u;    // 5 x 8B -> +16..55
    const uint32_t empty0   = hdr + 56u;    // +56..95
    const uint32_t sf_full0 = hdr + 96u;    // +96..135
    const uint32_t ready0   = hdr + 136u;   // +136..175 (rank0's are used)
    const uint32_t doneb    = hdr + 176u;
    const uint32_t slot     = hdr + 184u;

    if (wid == 0) TCGEN05_ALLOC_CG2(tmem_ptr_addr, 512);
    if (tid == 0) {
        #pragma unroll
        for (int s = 0; s < NSTAGE; s++) {
            MBARRIER_INIT(full0    + (uint32_t)s * 8u, 1);
            MBARRIER_INIT(empty0   + (uint32_t)s * 8u, 1);   // one cg2 commit per CTA
            MBARRIER_INIT(sf_full0 + (uint32_t)s * 8u, 4);
            MBARRIER_INIT(ready0   + (uint32_t)s * 8u, 2);   // both CTAs' gates
        }
        MBARRIER_INIT(doneb, 1);
    }
    __syncthreads();
    if (rank == 0 && tid == 0) {
        unsigned int t0 = atomicAdd(&g_tile_ctr, 1u);
        asm volatile("st.shared.u32 [%0], %1;" :: "r"(slot), "r"(t0) : "memory");
        ST_SLOT_REMOTE(slot, t0);
    }
    CLUSTER_SYNC();   // barriers valid cluster-wide + initial claim published

    uint32_t tmem;
    asm volatile("ld.shared.b32 %0, [%1];" : "=r"(tmem) : "r"(tmem_ptr_addr));
    uint32_t t;
    asm volatile("ld.shared.u32 %0, [%1];" : "=r"(t) : "r"(slot));

    const uint32_t warp_off = (uint32_t)(wid & 3) << 21;
    uint32_t gc = 0;          // s = gc%5, parity = (gc/5)&1
    uint32_t tile_cnt = 0;
    bool first = true;

    while (t < NPAIRS) {
        if (rank == 0 && tid == 0) {
            unsigned int tn_ = atomicAdd(&g_tile_ctr, 1u);
            asm volatile("st.shared.u32 [%0], %1;" :: "r"(slot), "r"(tn_) : "memory");
            ST_SLOT_REMOTE(slot, tn_);
        }
        CLUSTER_SYNC();   // publishes tn; orders prev epilogue TMEM reads before new MMAs
        uint32_t tn;
        asm volatile("ld.shared.u32 %0, [%1];" : "=r"(tn) : "r"(slot));

        // per-CTA coordinates: A rows = pair_m0 + rank*128; B rows = n0 + rank*128
        const int m0  = (int)(t / NT_X) * 256 + (int)rank * 128;
        const int n0  = (int)(t % NT_X) * 256;
        const int m0n = (int)(tn / NT_X) * 256 + (int)rank * 128;  // valid iff tn < NPAIRS
        const int n0n = (int)(tn % NT_X) * 256;
        const int brow  = n0  + (int)rank * 128;
        const int brown = n0n + (int)rank * 128;

        if (first) {
            if (wid == 1 && elect_one_pred()) {
                #pragma unroll
                for (int p = 0; p < NSTAGE; p++) {
                    const uint32_t fb = full0 + (uint32_t)p * 8u;
                    const uint32_t sa = base + (uint32_t)p * STAGE_BYTES;
                    MBARRIER_EXPECT_TX(fb, STAGE_TX);
                    TMA_LOAD_2D(sa,           &mapA,  p * 128, m0,    fb);
                    TMA_LOAD_2D(sa + A_BYTES, &mapB,  p * 128, brow,  fb);
                    TMA_LOAD_2D(sa + SFA_OFF, &mapSA, m0,      p * 4, fb);
                    TMA_LOAD_2D(sa + SFB_OFF, &mapSB, n0,      p * 4, fb);
                }
            } else if (wid >= 4) {
                #pragma unroll
                for (int p = 0; p < NSTAGE; p++) {
                    const uint32_t sa = base + (uint32_t)p * STAGE_BYTES;
                    MBARRIER_WAIT_PARITY(full0 + (uint32_t)p * 8u, 0u);
                    sf_fill_smem(tmem, p, sa, lid, warp_off);
                    TCGEN05_FENCE_BEFORE();
                    if (lid == 0) MBARRIER_ARRIVE(sf_full0 + (uint32_t)p * 8u);
                }
            }
            first = false;
        }

        for (int c = 0; c < NCHUNK; c++, gc++) {
            const int s = (int)(gc % 5u);
            const uint32_t par = (gc / 5u) & 1u;
            const uint32_t sa = base + (uint32_t)s * STAGE_BYTES;

            if (wid == 0) {
                if (rank == 0 && elect_one_pred()) {
                    // both CTAs' data + SF staged (gates arrived after local sf_full)
                    MBARRIER_WAIT_PARITY(ready0 + (uint32_t)s * 8u, par);
                    TCGEN05_FENCE_AFTER();
                    const uint64_t ad = make_desc(sa);
                    const uint64_t bd = make_desc(sa + A_BYTES);
                    const uint32_t sfbase = tmem + TMEM_SF + (uint32_t)s * SF_COLS;
                    #pragma unroll
                    for (int ks = 0; ks < 4; ks++) {
                        const uint32_t acc = (c > 0 || ks > 0) ? 1u : 0u;
                        const uint64_t ka = (uint64_t)(ks * 2);
                        mma_nvf4_ss_cg2(tmem + 0u, ad + ka, bd + ka, GEMM_IDESC,
                                        sfbase + (uint32_t)(ks * 4),
                                        sfbase + 16u + (uint32_t)(ks * 8), acc);
                    }
                    TCGEN05_COMMIT_MC_CG2(empty0 + (uint32_t)s * 8u, 3);
                }
            } else if (wid == 1) {
                if (elect_one_pred()) {
                    int cc = c + NSTAGE, kx, ya, yb, ysb;
                    bool valid;
                    if (cc < NCHUNK)      { valid = true;  kx = cc;          ya = m0;  yb = brow;  ysb = n0;  }
                    else if (tn < NPAIRS) { valid = true;  kx = cc - NCHUNK; ya = m0n; yb = brown; ysb = n0n; }
                    else                  { valid = false; kx = 0; ya = 0; yb = 0; ysb = 0; }
                    if (valid) {
                        MBARRIER_WAIT_PARITY(empty0 + (uint32_t)s * 8u, par);
                        MBARRIER_EXPECT_TX(full0 + (uint32_t)s * 8u, STAGE_TX);
                        TMA_LOAD_2D(sa,           &mapA,  kx * 128, ya,     full0 + (uint32_t)s * 8u);
                        TMA_LOAD_2D(sa + A_BYTES, &mapB,  kx * 128, yb,     full0 + (uint32_t)s * 8u);
                        TMA_LOAD_2D(sa + SFA_OFF, &mapSA, ya,       kx * 4, full0 + (uint32_t)s * 8u);
                        TMA_LOAD_2D(sa + SFB_OFF, &mapSB, ysb,      kx * 4, full0 + (uint32_t)s * 8u);
                    }
                }
            } else if (wid == 2) {
                if (elect_one_pred()) {
                    // gate: local stage ready (sf_full implies full via SF warps' acquire)
                    MBARRIER_WAIT_PARITY(sf_full0 + (uint32_t)s * 8u, par);
                    MBARRIER_ARRIVE_RANK0(ready0 + (uint32_t)s * 8u);
                }
            } else if (wid >= 4) {
                int cc = c + NSTAGE;
                bool valid = (cc < NCHUNK) || (tn < NPAIRS);
                if (valid) {
                    MBARRIER_WAIT_PARITY(empty0 + (uint32_t)s * 8u, par);        // TMEM SF free
                    MBARRIER_WAIT_PARITY(full0  + (uint32_t)s * 8u, par ^ 1u);   // slab arrived
                    sf_fill_smem(tmem, s, sa, lid, warp_off);
                    TCGEN05_FENCE_BEFORE();
                    if (lid == 0) MBARRIER_ARRIVE(sf_full0 + (uint32_t)s * 8u);
                }
            }
        }

        // Tile-done: one cg2 multicast commit after all chunks (in-order MMA).
        if (wid == 0 && rank == 0 && elect_one_pred()) TCGEN05_COMMIT_MC_CG2(doneb, 3);
        MBARRIER_WAIT_PARITY(doneb, tile_cnt & 1u);
        tile_cnt++;
        TCGEN05_FENCE_AFTER();

        // Epilogue (per-CTA): own 128 rows x 256 cols of D in own TMEM.
        {
            const int m = m0 + (wid & 3) * 32 + lid;
            const int nb = n0 + (wid >> 2) * 128;
            const uint32_t dbase = tmem + (uint32_t)((wid >> 2) * 128);
            float* orow = out + (size_t)m * N_DIM + nb;
            for (int cc2 = 0; cc2 < 128; cc2 += 32) {
                uint32_t d[32];
                TCGEN05_LD_32X32B_X32(d, dbase + (uint32_t)cc2);
                TCGEN05_WAIT_LD();
                const float4* b4 = reinterpret_cast<const float4*>(bias + nb + cc2);
                float4* o4 = reinterpret_cast<float4*>(orow + cc2);
                #pragma unroll
                for (int q = 0; q < 8; q++) {
                    float4 bv = __ldg(b4 + q);
                    float4 ov;
                    ov.x = __uint_as_float(d[q * 4 + 0]) + bv.x;
                    ov.y = __uint_as_float(d[q * 4 + 1]) + bv.y;
                    ov.z = __uint_as_float(d[q * 4 + 2]) + bv.z;
                    ov.w = __uint_as_float(d[q * 4 + 3]) + bv.w;
                    o4[q] = ov;
                }
            }
            TCGEN05_FENCE_BEFORE();
        }

        t = tn;
    }

    CLUSTER_SYNC();   // no CTA exits while peer work could target its SMEM/TMEM
    if (wid == 0) {
        TCGEN05_RELINQUISH_CG2();
        TCGEN05_DEALLOC_CG2(tmem, 512);
    }

#else
    // ------- baseline-pass fallback: correct SIMT decode GEMM (never selected) -------
    const int tt = blockIdx.x;
    const int m0 = (tt / NT_X) * 128;
    const int n0 = (tt % NT_X) * 256;
    for (int idx = tid; idx < 128 * 256; idx += GEMM_THREADS) {
        const int m = m0 + idx / 256;
        const int n = n0 + idx % 256;
        float acc = 0.0f;
        for (int G = 0; G < GPR; G++) {
            uint64_t av = g_xq4[(size_t)m * GPR + G];
            uint64_t bv = g_wq4[(size_t)n * GPR + G];
            __nv_fp8_e4m3 sa8, sb8;
            sa8.__x = (uint8_t)(g_sfa[(size_t)(G >> 2) * M_DIM + m] >> ((G & 3) * 8));
            sb8.__x = (uint8_t)(g_sfb[(size_t)(G >> 2) * N_DIM + n] >> ((G & 3) * 8));
            float fs = float(sa8) * float(sb8);
            float sum = 0.0f;
            #pragma unroll
            for (int i = 0; i < 16; i++) {
                uint32_t ca = (uint32_t)(av >> (4 * i)) & 15u;
                uint32_t cb = (uint32_t)(bv >> (4 * i)) & 15u;
                float va = c_lut[ca & 7u]; if (ca & 8u) va = -va;
                float vb = c_lut[cb & 7u]; if (cb & 8u) vb = -vb;
                sum += va * vb;
            }
            acc += sum * fs;
        }
        out[(size_t)m * N_DIM + n] = acc + __ldg(bias + n);
    }
#endif
}

// ---------------- host: tensormap encode ----------------
typedef CUresult (*PFN_encodeTiled)(
    CUtensorMap*, CUtensorMapDataType, cuuint32_t, void*,
    const cuuint64_t*, const cuuint64_t*, const cuuint32_t*, const cuuint32_t*,
    CUtensorMapInterleave, CUtensorMapSwizzle, CUtensorMapL2promotion,
    CUtensorMapFloatOOBfill);

static PFN_encodeTiled get_encoder() {
    void* p = nullptr;
    cudaDriverEntryPointQueryResult st;
    cudaGetDriverEntryPointByVersion("cuTensorMapEncodeTiled", &p, 12000,
                                     cudaEnableDefault, &st);
    return (PFN_encodeTiled)p;
}

static void encode_map_u8(CUtensorMap* map, void* ptr, uint64_t rows,
                          uint64_t row_bytes, uint32_t box_rows) {
    cuuint64_t dims[2]    = {row_bytes, rows};
    cuuint64_t strides[1] = {row_bytes};
    cuuint32_t box[2]     = {128, box_rows};
    cuuint32_t estr[2]    = {1, 1};
    get_encoder()(map, CU_TENSOR_MAP_DATA_TYPE_UINT8, 2, ptr,
       dims, strides, box, estr,
       CU_TENSOR_MAP_INTERLEAVE_NONE, CU_TENSOR_MAP_SWIZZLE_128B,
       CU_TENSOR_MAP_L2_PROMOTION_L2_128B,
       CU_TENSOR_MAP_FLOAT_OOB_FILL_NONE);
}

static void encode_map_sf(CUtensorMap* map, void* ptr, uint64_t cols, uint32_t box_cols) {
    cuuint64_t dims[2]    = {cols, GWR};
    cuuint64_t strides[1] = {cols * 4};
    cuuint32_t box[2]     = {box_cols, 4};
    cuuint32_t estr[2]    = {1, 1};
    get_encoder()(map, CU_TENSOR_MAP_DATA_TYPE_UINT32, 2, ptr,
       dims, strides, box, estr,
       CU_TENSOR_MAP_INTERLEAVE_NONE, CU_TENSOR_MAP_SWIZZLE_NONE,
       CU_TENSOR_MAP_L2_PROMOTION_L2_128B,
       CU_TENSOR_MAP_FLOAT_OOB_FILL_NONE);
}

// ---------------- launcher ----------------
extern "C" void kernel_launch(void* const* d_in, const int* in_sizes, int n_in,
                              void* d_out, int out_size) {
    (void)in_sizes; (void)n_in; (void)out_size;
    const float* x    = (const float*)d_in[0];
    const float* w    = (const float*)d_in[1];
    const float* bias = (const float*)d_in[2];
    float* out = (float*)d_out;

    uint64_t *xq4 = nullptr, *wq4 = nullptr;
    uint32_t *sfa = nullptr, *sfb = nullptr;
    cudaGetSymbolAddress((void**)&xq4, g_xq4);
    cudaGetSymbolAddress((void**)&wq4, g_wq4);
    cudaGetSymbolAddress((void**)&sfa, g_sfa);
    cudaGetSymbolAddress((void**)&sfb, g_sfb);

    CUtensorMap mapA, mapB, mapSA, mapSB;
    encode_map_u8(&mapA, xq4, M_DIM, K_DIM / 2, 128);
    encode_map_u8(&mapB, wq4, N_DIM, K_DIM / 2, 128);   // 128-N-row half per CTA
    encode_map_sf(&mapSA, sfa, M_DIM, 128);
    encode_map_sf(&mapSB, sfb, N_DIM, 256);             // full-N SFB per CTA

    const int xg = M_DIM * GPR;
    const int wg = N_DIM * GPR;
    quant_fp4_kernel<<<xg / 256, 256>>>(x, xq4, (uint8_t*)sfa, M_DIM, xg);
    quant_fp4_kernel<<<wg / 256, 256>>>(w, wq4, (uint8_t*)sfb, N_DIM, wg);

    reset_ctr_kernel<<<1, 1>>>();

    cudaFuncSetAttribute(gemm_fp4, cudaFuncAttributeMaxDynamicSharedMemorySize, GEMM_SMEM_BYTES);
    gemm_fp4<<<NPAIRS * 2, GEMM_THREADS, GEMM_SMEM_BYTES>>>(mapA, mapB, mapSA, mapSB, bias, out);
}

// round 11
// speedup vs baseline: 1.1938x; 1.1701x over previous
#include <cuda_runtime.h>
#include <cuda.h>
#include <cuda_bf16.h>
#include <cuda_fp8.h>
#include <stdint.h>

#define M_DIM 8192
#define K_DIM 4096
#define N_DIM 4096
#define GPR (K_DIM / 16)   // 256 groups/row
#define GWR (K_DIM / 64)   // 64 SF words/row
#define XBLOCKS (M_DIM * GPR / 256)   // 8192
#define WBLOCKS (N_DIM * GPR / 256)   // 4096

#if defined(__CUDA_ARCH__) && (__CUDA_ARCH__ >= 1000) && \
    (defined(__CUDA_ARCH_FEAT_SM103_ALL) || defined(__CUDA_ARCH_FEAT_SM100_ALL) || \
     defined(__CUDA_ARCH_SPECIFIC__) || defined(__CUDA_ARCH_FAMILY_SPECIFIC__))
#define USE_TCGEN05 1
#else
#define USE_TCGEN05 0
#endif

// ---------------- scratch ----------------
__device__ uint64_t g_xq4[(size_t)M_DIM * GPR];   // packed e2m1 x, 16 MB
__device__ uint64_t g_wq4[(size_t)N_DIM * GPR];   // packed e2m1 w,  8 MB
__device__ uint32_t g_sfa[(size_t)GWR * M_DIM];   // SF words [gw][m]
__device__ uint32_t g_sfb[(size_t)GWR * N_DIM];   // SF words [gw][n]
__device__ unsigned int g_tile_ctr;
__constant__ float c_lut[8] = {0.f, 0.5f, 1.f, 1.5f, 2.f, 3.f, 4.f, 6.f};

__device__ __forceinline__ uint32_t smem_u32(const void* p) {
    uint32_t a;
    asm("{ .reg .u64 t; cvta.to.shared.u64 t, %1; cvt.u32.u64 %0, t; }" : "=r"(a) : "l"(p));
    return a;
}

#if USE_TCGEN05
__device__ __forceinline__ uint32_t elect_one_pred() {
    uint32_t pred;
    asm volatile("{\n\t.reg .pred p;\n\telect.sync _|p, 0xFFFFFFFF;\n\t"
                 "selp.b32 %0, 1, 0, p;\n\t}" : "=r"(pred));
    return pred;
}

#define MBARRIER_INIT(addr, cnt) \
    asm volatile("mbarrier.init.shared.b64 [%0], %1;" :: "r"((uint32_t)(addr)), "r"((uint32_t)(cnt)) : "memory")
#define MBARRIER_ARRIVE(addr) \
    asm volatile("mbarrier.arrive.shared.b64 _, [%0];" :: "r"((uint32_t)(addr)) : "memory")
#define MBARRIER_EXPECT_TX(addr, bytes) \
    asm volatile("mbarrier.arrive.expect_tx.shared.b64 _, [%0], %1;" \
        :: "r"((uint32_t)(addr)), "r"((uint32_t)(bytes)) : "memory")
#define MBARRIER_WAIT_PARITY(mbar_smem_addr, phase_parity) do { \
    uint32_t _mbar = (uint32_t)(mbar_smem_addr); \
    uint32_t _parity = (uint32_t)(phase_parity); \
    uint32_t _done; \
    asm volatile("{\n\t.reg .pred p;\n\t" \
        "mbarrier.try_wait.parity.acquire.cta.shared::cta.b64 p, [%1], %2;\n\t" \
        "selp.b32 %0, 1, 0, p;\n\t}" : "=r"(_done) : "r"(_mbar), "r"(_parity) : "memory"); \
    if (!_done) { \
        asm volatile("{\n\t.reg .pred P1;\n\t" \
            "WAIT_LOOP_%=:\n\t" \
            "mbarrier.try_wait.parity.acquire.cta.shared::cta.b64 P1, [%0], %1, 0x989680;\n\t" \
            "@P1 bra.uni WAIT_DONE_%=;\n\t" \
            "bra.uni WAIT_LOOP_%=;\n\t" \
            "WAIT_DONE_%=:\n\t}" :: "r"(_mbar), "r"(_parity) : "memory"); \
    } \
} while (0)

#define TMA_LOAD_2D(smem_addr, map_ptr, cx, cy, mbar) \
    asm volatile("cp.async.bulk.tensor.2d.shared::cta.global.tile.mbarrier::complete_tx::bytes " \
        "[%0], [%1, {%2, %3}], [%4];" \
        :: "r"((uint32_t)(smem_addr)), "l"(map_ptr), "r"((int)(cx)), "r"((int)(cy)), \
           "r"((uint32_t)(mbar)) : "memory")

#define TCGEN05_ALLOC(a, n) \
    asm volatile("tcgen05.alloc.cta_group::1.sync.aligned.shared::cta.b32 [%0], %1;" \
        :: "r"((uint32_t)(a)), "r"((uint32_t)(n)) : "memory")
#define TCGEN05_DEALLOC(t, n) \
    asm volatile("tcgen05.dealloc.cta_group::1.sync.aligned.b32 %0, %1;" :: "r"(t), "r"((uint32_t)(n)))
#define TCGEN05_RELINQUISH() \
    asm volatile("tcgen05.relinquish_alloc_permit.cta_group::1.sync.aligned;")
#define TCGEN05_COMMIT(m) \
    asm volatile("tcgen05.commit.cta_group::1.mbarrier::arrive::one.shared::cluster.b64 [%0];" \
        :: "r"((uint32_t)(m)) : "memory")
#define TCGEN05_WAIT_LD() asm volatile("tcgen05.wait::ld.sync.aligned;" ::: "memory")
#define TCGEN05_WAIT_ST() asm volatile("tcgen05.wait::st.sync.aligned;" ::: "memory")
#define TCGEN05_FENCE_AFTER()  asm volatile("tcgen05.fence::after_thread_sync;" ::: "memory")
#define TCGEN05_FENCE_BEFORE() asm volatile("tcgen05.fence::before_thread_sync;" ::: "memory")

#define LDS32(r, addr) \
    asm volatile("ld.shared.b32 %0, [%1];" : "=r"(r) : "r"((uint32_t)(addr)))

#define TCGEN05_LD_32X32B_X32(r, tmem_addr) \
    asm volatile("tcgen05.ld.sync.aligned.32x32b.x32.b32 " \
        "{%0, %1, %2, %3, %4, %5, %6, %7, " \
        " %8, %9, %10, %11, %12, %13, %14, %15, " \
        " %16, %17, %18, %19, %20, %21, %22, %23, " \
        " %24, %25, %26, %27, %28, %29, %30, %31}, [%32];" \
        : "=r"((r)[0]),  "=r"((r)[1]),  "=r"((r)[2]),  "=r"((r)[3]), \
          "=r"((r)[4]),  "=r"((r)[5]),  "=r"((r)[6]),  "=r"((r)[7]), \
          "=r"((r)[8]),  "=r"((r)[9]),  "=r"((r)[10]), "=r"((r)[11]), \
          "=r"((r)[12]), "=r"((r)[13]), "=r"((r)[14]), "=r"((r)[15]), \
          "=r"((r)[16]), "=r"((r)[17]), "=r"((r)[18]), "=r"((r)[19]), \
          "=r"((r)[20]), "=r"((r)[21]), "=r"((r)[22]), "=r"((r)[23]), \
          "=r"((r)[24]), "=r"((r)[25]), "=r"((r)[26]), "=r"((r)[27]), \
          "=r"((r)[28]), "=r"((r)[29]), "=r"((r)[30]), "=r"((r)[31]) \
        : "r"(tmem_addr))

__device__ __forceinline__ void ttst4(uint32_t addr, uint32_t r0, uint32_t r1,
                                      uint32_t r2, uint32_t r3) {
    asm volatile("tcgen05.st.sync.aligned.32x32b.x4.b32 [%0], {%1, %2, %3, %4};"
        :: "r"(addr), "r"(r0), "r"(r1), "r"(r2), "r"(r3) : "memory");
}

__device__ __forceinline__ uint64_t make_desc(uint32_t addr) {
    const uint64_t base = (2ull << 61) | (1ull << 46) | (64ull << 32) | (1ull << 16);
    return base | ((uint64_t)(addr >> 4) & 0x3FFFull);
}

// nvf4: e2m1 data (SMEM SS), ue4m3 SF (TMEM), scale_vec::4X, fp32 accum.
__device__ __forceinline__ void mma_nvf4_ss(uint32_t d, uint64_t a_desc, uint64_t b_desc,
                                            uint32_t idesc, uint32_t sfa, uint32_t sfb,
                                            uint32_t acc) {
    asm volatile("{\n\t.reg .pred p;\n\tsetp.ne.u32 p, %6, 0;\n\t"
        "tcgen05.mma.cta_group::1.kind::mxf4nvf4.block_scale.scale_vec::4X "
        "[%0], %1, %2, %3, [%4], [%5], p;\n\t}"
        :: "r"(d), "l"(a_desc), "l"(b_desc), "r"(idesc), "r"(sfa), "r"(sfb), "r"(acc)
        : "memory");
}
#endif  // USE_TCGEN05

// ---------------- merged quant: fp32 -> packed e2m1 + e4m3 SF ----------------
// Binary-search bucketing == proven linear chain (code = #thresholds <= a):
//   b2: a>=t3 splits {0..3}/{4..7}; b1: a>=t1|t5; b0: a>=t0|t2|t4|t6.
// All thresholds tX*scale exact in fp32 (<=3 mantissa bits each side).
__global__ void __launch_bounds__(256) quant_both_kernel(
    const float* __restrict__ x, const float* __restrict__ w,
    uint64_t* __restrict__ xq, uint64_t* __restrict__ wq,
    uint8_t* __restrict__ sfx, uint8_t* __restrict__ sfw)
{
    const int b = blockIdx.x;
    if (b == 0 && threadIdx.x == 0) g_tile_ctr = 0u;   // stream-ordered before GEMM

    const float* in;
    uint64_t* outq;
    uint8_t* sfp;
    int nrows, g;
    if (b < XBLOCKS) { in = x; outq = xq; sfp = sfx; nrows = M_DIM; g = b * 256 + threadIdx.x; }
    else             { in = w; outq = wq; sfp = sfw; nrows = N_DIM; g = (b - XBLOCKS) * 256 + threadIdx.x; }

    const float4* p = reinterpret_cast<const float4*>(in) + (size_t)g * 4;
    float v[16];
    {
        float4 q0 = p[0], q1 = p[1], q2 = p[2], q3 = p[3];
        v[0]=q0.x; v[1]=q0.y; v[2]=q0.z;  v[3]=q0.w;
        v[4]=q1.x; v[5]=q1.y; v[6]=q1.z;  v[7]=q1.w;
        v[8]=q2.x; v[9]=q2.y; v[10]=q2.z; v[11]=q2.w;
        v[12]=q3.x; v[13]=q3.y; v[14]=q3.z; v[15]=q3.w;
    }
    float amax = 0.0f;
    #pragma unroll
    for (int i = 0; i < 16; i++) amax = fmaxf(amax, fabsf(v[i]));

    float sraw = __fdiv_rn(amax, 6.0f);
    __nv_fp8_e4m3 s8(sraw);
    float scale = float(s8);

    uint32_t lo = 0, hi = 0;
    if (scale > 0.0f) {
        const float t0 = 0.25f * scale, t1 = 0.75f * scale, t2 = 1.25f * scale,
                    t3 = 1.75f * scale, t4 = 2.5f * scale,  t5 = 3.5f * scale,
                    t6 = 5.0f * scale;
        #pragma unroll
        for (int i = 0; i < 16; i++) {
            const float a = fabsf(v[i]);
            const bool b2 = (a >= t3);
            const float tb1 = b2 ? t5 : t1;
            const bool b1 = (a >= tb1);
            const float tb0 = b2 ? (b1 ? t6 : t4) : (b1 ? t2 : t0);
            const bool b0 = (a >= tb0);
            uint32_t code = ((uint32_t)b2 << 2) | ((uint32_t)b1 << 1) | (uint32_t)b0;
            code |= (__float_as_uint(v[i]) >> 28) & 8u;   // sign nibble bit
            if (i < 8) lo |= code << (4 * i);
            else       hi |= code << (4 * (i - 8));
        }
    }
    uint2 pk;
    pk.x = lo;
    pk.y = hi;
    reinterpret_cast<uint2*>(outq)[g] = pk;

    const int m = g / GPR;
    const int G = g % GPR;
    sfp[(((size_t)(G >> 2)) * (size_t)nrows + (size_t)m) * 4 + (size_t)(G & 3)] = s8.__x;
}

// ---------------- GEMM (exact R8 architecture: proven 102.5 us) ----------------
#define BM 128
#define BN 256
#define GEMM_THREADS 256
#define NCHUNK 16
#define NT_X (N_DIM / BN)               // 16
#define NTILES ((M_DIM / BM) * NT_X)    // 1024
#define NSTAGE 4
#define A_BYTES 16384
#define B_BYTES 32768
#define SFA_OFF (A_BYTES + B_BYTES)     // 49152
#define SFB_OFF (SFA_OFF + 2048)        // 51200
#define STAGE_BYTES 55296
#define STAGE_TX 55296
#define TMEM_SF 256
#define SF_COLS 48
#define GEMM_IDESC ((1u << 7) | (1u << 10) | (16u << 17) | (1u << 27))
#define HDR_OFF (NSTAGE * STAGE_BYTES)  // 221184
#define GEMM_SMEM_BYTES (HDR_OFF + 128 + 1024)

#if USE_TCGEN05
__device__ __forceinline__ void sf_fill_smem(uint32_t tmem, int s, uint32_t sa,
                                             int lid, uint32_t warp_off) {
    const uint32_t sfbase = tmem + TMEM_SF + (uint32_t)s * SF_COLS;
    const uint32_t pA = sa + SFA_OFF;
    const uint32_t pB = sa + SFB_OFF;
    #pragma unroll
    for (int ks = 0; ks < 4; ks++) {
        uint32_t a0, a1, a2, a3;
        LDS32(a0, pA + (uint32_t)(ks * 128 +   0 + lid) * 4u);
        LDS32(a1, pA + (uint32_t)(ks * 128 +  32 + lid) * 4u);
        LDS32(a2, pA + (uint32_t)(ks * 128 +  64 + lid) * 4u);
        LDS32(a3, pA + (uint32_t)(ks * 128 +  96 + lid) * 4u);
        ttst4(sfbase + (uint32_t)(ks * 4) + warp_off, a0, a1, a2, a3);
        uint32_t bv[8];
        #pragma unroll
        for (int j = 0; j < 8; j++)
            LDS32(bv[j], pB + (uint32_t)(ks * 256 + j * 32 + lid) * 4u);
        ttst4(sfbase + 16u + (uint32_t)(ks * 8) + warp_off,      bv[0], bv[1], bv[2], bv[3]);
        ttst4(sfbase + 16u + (uint32_t)(ks * 8) + 4u + warp_off, bv[4], bv[5], bv[6], bv[7]);
    }
    TCGEN05_WAIT_ST();
}
#endif

__global__ void __launch_bounds__(GEMM_THREADS, 1)
gemm_fp4(const __grid_constant__ CUtensorMap mapA,
         const __grid_constant__ CUtensorMap mapB,
         const __grid_constant__ CUtensorMap mapSA,
         const __grid_constant__ CUtensorMap mapSB,
         const float* __restrict__ bias,
         float* __restrict__ out)
{
    extern __shared__ char smem_raw[];
    const int tid = threadIdx.x;
    const int wid = tid >> 5;
    const int lid = tid & 31;

#if USE_TCGEN05
    const uint32_t base = (smem_u32(smem_raw) + 1023u) & ~1023u;
    const uint32_t hdr = base + HDR_OFF;
    const uint32_t tmem_ptr_addr = hdr;
    const uint32_t full0    = hdr + 16u;
    const uint32_t empty0   = hdr + 48u;
    const uint32_t sf_full0 = hdr + 80u;
    const uint32_t doneb    = hdr + 112u;
    const uint32_t slot     = hdr + 120u;

    if (wid == 0) TCGEN05_ALLOC(tmem_ptr_addr, 512);
    if (tid == 0) {
        #pragma unroll
        for (int s = 0; s < NSTAGE; s++) {
            MBARRIER_INIT(full0    + (uint32_t)s * 8u, 1);
            MBARRIER_INIT(empty0   + (uint32_t)s * 8u, 1);
            MBARRIER_INIT(sf_full0 + (uint32_t)s * 8u, 4);
        }
        MBARRIER_INIT(doneb, 1);
        unsigned int t0 = atomicAdd(&g_tile_ctr, 1u);
        asm volatile("st.shared.u32 [%0], %1;" :: "r"(slot), "r"(t0) : "memory");
    }
    __syncthreads();

    uint32_t tmem;
    asm volatile("ld.shared.b32 %0, [%1];" : "=r"(tmem) : "r"(tmem_ptr_addr));
    uint32_t t;
    asm volatile("ld.shared.u32 %0, [%1];" : "=r"(t) : "r"(slot));

    const uint32_t warp_off = (uint32_t)(wid & 3) << 21;
    uint32_t gc = 0;          // s = gc&3, parity = (gc>>2)&1
    uint32_t tile_cnt = 0;
    bool first = true;

    while (t < NTILES) {
        if (tid == 0) {
            unsigned int tn_ = atomicAdd(&g_tile_ctr, 1u);
            asm volatile("st.shared.u32 [%0], %1;" :: "r"(slot), "r"(tn_) : "memory");
        }
        __syncthreads();
        uint32_t tn;
        asm volatile("ld.shared.u32 %0, [%1];" : "=r"(tn) : "r"(slot));

        const int m0  = (int)(t / NT_X) * BM;
        const int n0  = (int)(t % NT_X) * BN;
        const int m0n = (int)(tn / NT_X) * BM;    // valid only if tn < NTILES
        const int n0n = (int)(tn % NT_X) * BN;

        if (first) {
            if (wid == 1 && elect_one_pred()) {
                #pragma unroll
                for (int p = 0; p < NSTAGE; p++) {
                    const uint32_t fb = full0 + (uint32_t)p * 8u;
                    const uint32_t sa = base + (uint32_t)p * STAGE_BYTES;
                    MBARRIER_EXPECT_TX(fb, STAGE_TX);
                    TMA_LOAD_2D(sa,           &mapA,  p * 128, m0,    fb);
                    TMA_LOAD_2D(sa + A_BYTES, &mapB,  p * 128, n0,    fb);
                    TMA_LOAD_2D(sa + SFA_OFF, &mapSA, m0,      p * 4, fb);
                    TMA_LOAD_2D(sa + SFB_OFF, &mapSB, n0,      p * 4, fb);
                }
            } else if (wid >= 4) {
                #pragma unroll
                for (int p = 0; p < NSTAGE; p++) {
                    const uint32_t sa = base + (uint32_t)p * STAGE_BYTES;
                    MBARRIER_WAIT_PARITY(full0 + (uint32_t)p * 8u, 0u);
                    sf_fill_smem(tmem, p, sa, lid, warp_off);
                    TCGEN05_FENCE_BEFORE();
                    if (lid == 0) MBARRIER_ARRIVE(sf_full0 + (uint32_t)p * 8u);
                }
            }
            first = false;
        }

        for (int c = 0; c < NCHUNK; c++, gc++) {
            const int s = (int)(gc & 3u);
            const uint32_t par = (gc >> 2) & 1u;
            const uint32_t sa = base + (uint32_t)s * STAGE_BYTES;

            if (wid == 0) {
                if (elect_one_pred()) {
                    MBARRIER_WAIT_PARITY(sf_full0 + (uint32_t)s * 8u, par);
                    TCGEN05_FENCE_AFTER();
                    const uint64_t ad  = make_desc(sa);
                    const uint64_t bd0 = make_desc(sa + 16384u);
                    const uint64_t bd1 = make_desc(sa + 32768u);
                    const uint32_t sfbase = tmem + TMEM_SF + (uint32_t)s * SF_COLS;
                    #pragma unroll
                    for (int ks = 0; ks < 4; ks++) {
                        const uint32_t acc = (c > 0 || ks > 0) ? 1u : 0u;
                        const uint64_t ka = (uint64_t)(ks * 2);
                        const uint32_t sfa  = sfbase + (uint32_t)(ks * 4);
                        const uint32_t sfb0 = sfbase + 16u + (uint32_t)(ks * 8);
                        mma_nvf4_ss(tmem + 0u,   ad + ka, bd0 + ka, GEMM_IDESC, sfa, sfb0,      acc);
                        mma_nvf4_ss(tmem + 128u, ad + ka, bd1 + ka, GEMM_IDESC, sfa, sfb0 + 4u, acc);
                    }
                    TCGEN05_COMMIT(empty0 + (uint32_t)s * 8u);
                }
            } else if (wid == 1) {
                if (elect_one_pred()) {
                    int cc = c + NSTAGE, kx, ya, yb;
                    bool valid;
                    if (cc < NCHUNK)      { valid = true;  kx = cc;          ya = m0;  yb = n0;  }
                    else if (tn < NTILES) { valid = true;  kx = cc - NCHUNK; ya = m0n; yb = n0n; }
                    else                  { valid = false; kx = 0; ya = 0; yb = 0; }
                    if (valid) {
                        MBARRIER_WAIT_PARITY(empty0 + (uint32_t)s * 8u, par);
                        MBARRIER_EXPECT_TX(full0 + (uint32_t)s * 8u, STAGE_TX);
                        TMA_LOAD_2D(sa,           &mapA,  kx * 128, ya,     full0 + (uint32_t)s * 8u);
                        TMA_LOAD_2D(sa + A_BYTES, &mapB,  kx * 128, yb,     full0 + (uint32_t)s * 8u);
                        TMA_LOAD_2D(sa + SFA_OFF, &mapSA, ya,       kx * 4, full0 + (uint32_t)s * 8u);
                        TMA_LOAD_2D(sa + SFB_OFF, &mapSB, yb,       kx * 4, full0 + (uint32_t)s * 8u);
                    }
                }
            } else if (wid >= 4) {
                int cc = c + NSTAGE;
                bool valid = (cc < NCHUNK) || (tn < NTILES);
                if (valid) {
                    MBARRIER_WAIT_PARITY(empty0 + (uint32_t)s * 8u, par);        // TMEM SF free
                    MBARRIER_WAIT_PARITY(full0  + (uint32_t)s * 8u, par ^ 1u);   // slab arrived
                    sf_fill_smem(tmem, s, sa, lid, warp_off);
                    TCGEN05_FENCE_BEFORE();
                    if (lid == 0) MBARRIER_ARRIVE(sf_full0 + (uint32_t)s * 8u);
                }
            }
        }

        // Tile-done: one commit after all chunks (in-order MMA). Alias-safe per R5.
        if (wid == 0 && elect_one_pred()) TCGEN05_COMMIT(doneb);
        MBARRIER_WAIT_PARITY(doneb, tile_cnt & 1u);
        tile_cnt++;
        TCGEN05_FENCE_AFTER();

        // Epilogue: warp w -> rows m0+(w&3)*32+lid, cols (w>>2)*128..+127.
        {
            const int m = m0 + (wid & 3) * 32 + lid;
            const int nb = n0 + (wid >> 2) * 128;
            const uint32_t dbase = tmem + (uint32_t)((wid >> 2) * 128);
            float* orow = out + (size_t)m * N_DIM + nb;
            for (int cc2 = 0; cc2 < 128; cc2 += 32) {
                uint32_t d[32];
                TCGEN05_LD_32X32B_X32(d, dbase + (uint32_t)cc2);
                TCGEN05_WAIT_LD();
                const float4* b4 = reinterpret_cast<const float4*>(bias + nb + cc2);
                float4* o4 = reinterpret_cast<float4*>(orow + cc2);
                #pragma unroll
                for (int q = 0; q < 8; q++) {
                    float4 bv = __ldg(b4 + q);
                    float4 ov;
                    ov.x = __uint_as_float(d[q * 4 + 0]) + bv.x;
                    ov.y = __uint_as_float(d[q * 4 + 1]) + bv.y;
                    ov.z = __uint_as_float(d[q * 4 + 2]) + bv.z;
                    ov.w = __uint_as_float(d[q * 4 + 3]) + bv.w;
                    o4[q] = ov;
                }
            }
            TCGEN05_FENCE_BEFORE();
        }

        t = tn;
    }

    __syncthreads();
    if (wid == 0) {
        TCGEN05_RELINQUISH();
        TCGEN05_DEALLOC(tmem, 512);
    }

#else
    // ------- baseline-pass fallback: correct SIMT decode GEMM (never selected) -------
    const int tt = blockIdx.x;
    const int m0 = (tt / NT_X) * BM;
    const int n0 = (tt % NT_X) * BN;
    for (int idx = tid; idx < BM * BN; idx += GEMM_THREADS) {
        const int m = m0 + idx / BN;
        const int n = n0 + idx % BN;
        float acc = 0.0f;
        for (int G = 0; G < GPR; G++) {
            uint64_t av = g_xq4[(size_t)m * GPR + G];
            uint64_t bv = g_wq4[(size_t)n * GPR + G];
            __nv_fp8_e4m3 sa8, sb8;
            sa8.__x = (uint8_t)(g_sfa[(size_t)(G >> 2) * M_DIM + m] >> ((G & 3) * 8));
            sb8.__x = (uint8_t)(g_sfb[(size_t)(G >> 2) * N_DIM + n] >> ((G & 3) * 8));
            float fs = float(sa8) * float(sb8);
            float sum = 0.0f;
            #pragma unroll
            for (int i = 0; i < 16; i++) {
                uint32_t ca = (uint32_t)(av >> (4 * i)) & 15u;
                uint32_t cb = (uint32_t)(bv >> (4 * i)) & 15u;
                float va = c_lut[ca & 7u]; if (ca & 8u) va = -va;
                float vb = c_lut[cb & 7u]; if (cb & 8u) vb = -vb;
                sum += va * vb;
            }
            acc += sum * fs;
        }
        out[(size_t)m * N_DIM + n] = acc + __ldg(bias + n);
    }
#endif
}

// ---------------- host: tensormap encode ----------------
typedef CUresult (*PFN_encodeTiled)(
    CUtensorMap*, CUtensorMapDataType, cuuint32_t, void*,
    const cuuint64_t*, const cuuint64_t*, const cuuint32_t*, const cuuint32_t*,
    CUtensorMapInterleave, CUtensorMapSwizzle, CUtensorMapL2promotion,
    CUtensorMapFloatOOBfill);

static PFN_encodeTiled get_encoder() {
    void* p = nullptr;
    cudaDriverEntryPointQueryResult st;
    cudaGetDriverEntryPointByVersion("cuTensorMapEncodeTiled", &p, 12000,
                                     cudaEnableDefault, &st);
    return (PFN_encodeTiled)p;
}

static void encode_map_u8(CUtensorMap* map, void* ptr, uint64_t rows,
                          uint64_t row_bytes, uint32_t box_rows) {
    cuuint64_t dims[2]    = {row_bytes, rows};
    cuuint64_t strides[1] = {row_bytes};
    cuuint32_t box[2]     = {128, box_rows};
    cuuint32_t estr[2]    = {1, 1};
    get_encoder()(map, CU_TENSOR_MAP_DATA_TYPE_UINT8, 2, ptr,
       dims, strides, box, estr,
       CU_TENSOR_MAP_INTERLEAVE_NONE, CU_TENSOR_MAP_SWIZZLE_128B,
       CU_TENSOR_MAP_L2_PROMOTION_L2_128B,
       CU_TENSOR_MAP_FLOAT_OOB_FILL_NONE);
}

static void encode_map_sf(CUtensorMap* map, void* ptr, uint64_t cols, uint32_t box_cols) {
    cuuint64_t dims[2]    = {cols, GWR};
    cuuint64_t strides[1] = {cols * 4};
    cuuint32_t box[2]     = {box_cols, 4};
    cuuint32_t estr[2]    = {1, 1};
    get_encoder()(map, CU_TENSOR_MAP_DATA_TYPE_UINT32, 2, ptr,
       dims, strides, box, estr,
       CU_TENSOR_MAP_INTERLEAVE_NONE, CU_TENSOR_MAP_SWIZZLE_NONE,
       CU_TENSOR_MAP_L2_PROMOTION_L2_128B,
       CU_TENSOR_MAP_FLOAT_OOB_FILL_NONE);
}

// ---------------- launcher ----------------
extern "C" void kernel_launch(void* const* d_in, const int* in_sizes, int n_in,
                              void* d_out, int out_size) {
    (void)in_sizes; (void)n_in; (void)out_size;
    const float* x    = (const float*)d_in[0];
    const float* w    = (const float*)d_in[1];
    const float* bias = (const float*)d_in[2];
    float* out = (float*)d_out;

    uint64_t *xq4 = nullptr, *wq4 = nullptr;
    uint32_t *sfa = nullptr, *sfb = nullptr;
    cudaGetSymbolAddress((void**)&xq4, g_xq4);
    cudaGetSymbolAddress((void**)&wq4, g_wq4);
    cudaGetSymbolAddress((void**)&sfa, g_sfa);
    cudaGetSymbolAddress((void**)&sfb, g_sfb);

    CUtensorMap mapA, mapB, mapSA, mapSB;
    encode_map_u8(&mapA, xq4, M_DIM, K_DIM / 2, 128);
    encode_map_u8(&mapB, wq4, N_DIM, K_DIM / 2, 256);
    encode_map_sf(&mapSA, sfa, M_DIM, 128);
    encode_map_sf(&mapSB, sfb, N_DIM, 256);

    // one merged launch: x-quant blocks [0, XBLOCKS), w-quant [XBLOCKS, XBLOCKS+WBLOCKS);
    // also resets the GEMM tile counter (stream-ordered before gemm_fp4).
    quant_both_kernel<<<XBLOCKS + WBLOCKS, 256>>>(x, w, xq4, wq4,
                                                  (uint8_t*)sfa, (uint8_t*)sfb);

    cudaFuncSetAttribute(gemm_fp4, cudaFuncAttributeMaxDynamicSharedMemorySize, GEMM_SMEM_BYTES);
    gemm_fp4<<<NTILES, GEMM_THREADS, GEMM_SMEM_BYTES>>>(mapA, mapB, mapSA, mapSB, bias, out);
}